// round 8
// baseline (speedup 1.0000x reference)
#include <cuda_runtime.h>
#include <cuda_bf16.h>

#define HH 4096
#define WW 4096
#define NPIX (HH*WW)           // 16777216
#define W3  (3*WW)             // 12288
#define GRAD_BASE 50331648     // H*3W, relative to o = out+1
#define GRID_X 4
#define BLK 256
#define RTILE 8
#define NROWBLK (HH/RTILE)       // 512
#define NBLOCKS (GRID_X*NROWBLK) // 2048

__device__ float g_partials[NBLOCKS];
__device__ unsigned int g_counter = 0u;

__device__ __forceinline__ float frcp(float x) {
    float y; asm("rcp.approx.f32 %0, %1;" : "=f"(y) : "f"(x)); return y;
}
__device__ __forceinline__ float fex2(float x) {
    float y; asm("ex2.approx.f32 %0, %1;" : "=f"(y) : "f"(x)); return y;
}
__device__ __forceinline__ float ldcg_f(const float* p) {
    float v; asm volatile("ld.global.cg.f32 %0, [%1];" : "=f"(v) : "l"(p)); return v;
}
__device__ __forceinline__ unsigned int atom_inc_acqrel(unsigned int* p) {
    unsigned int prev;
    asm volatile("atom.global.add.acq_rel.gpu.u32 %0, [%1], 1;"
                 : "=r"(prev) : "l"(p) : "memory");
    return prev;
}

__constant__ float NEG5LOG2E = -7.213475204444817f; // -5 / ln(2)
#define EPSV 1e-5f

// Fully general scalar path for boundary pixels.
__device__ __forceinline__ float do_pixel(int i, int j,
        const float* __restrict__ T, const float* __restrict__ K,
        const float* __restrict__ S, float* __restrict__ o)
{
    int idx = i*WW + j;
    float t = T[idx], s = S[idx], k = K[idx];
    float m  = (s != 0.f) ? k : 0.f;
    float sm = s * k;

    float gbx = 0.f, gsx = 0.f, gmx;
    if (j < WW-1) {
        float sr = S[idx+1], kr = K[idx+1];
        float mr = (sr != 0.f) ? kr : 0.f;
        gbx = T[idx+1] - t;
        gsx = sr*kr - sm;
        gmx = mr - m;
    } else {
        float sl = S[idx-1], kl = K[idx-1];
        gmx = m - ((sl != 0.f) ? kl : 0.f);
    }

    float gby = 0.f, gsy = 0.f, gmy;
    if (i < HH-1) {
        float sd = S[idx+WW], kd = K[idx+WW];
        float md = (sd != 0.f) ? kd : 0.f;
        gby = T[idx+WW] - t;
        gsy = sd*kd - sm;
        gmy = md - m;
    } else {
        float su = S[idx-WW], ku = K[idx-WW];
        gmy = m - ((su != 0.f) ? ku : 0.f);
    }

    if (gmx != 0.f || gmy != 0.f) { gbx = 0.f; gby = 0.f; }

    float rc = fabsf(frcp(sm + EPSV)) * NEG5LOG2E;
    float wx = m * fex2(fabsf(gsx) * rc);
    float wy = m * fex2(fabsf(gsy) * rc);

    int wb = i*W3 + j;
    __stcs(o + wb,        wx);
    __stcs(o + wb + WW,   wy);
    __stcs(o + wb + 2*WW, 0.f);
    int gb = GRAD_BASE + idx;
    __stcs(o + gb,          gbx);
    __stcs(o + gb + NPIX,   gby);
    __stcs(o + gb + 2*NPIX, gsx);
    __stcs(o + gb + 3*NPIX, gsy);

    float dx = wx * (gbx - gsx);
    float dy = wy * (gby - gsy);
    return fmaf(dx, dx, dy*dy);
}

__global__ __launch_bounds__(BLK)
void wpbl_main(const float* __restrict__ T, const float* __restrict__ K,
               const float* __restrict__ S, float* __restrict__ out)
{
    const int r0 = blockIdx.y * RTILE;
    const int u = blockIdx.x * BLK + threadIdx.x;     // 0..1023
    const int lane = threadIdx.x & 31;
    float* o = out + 1;
    float acc = 0.f;
    const bool vec = (u < 1023);
    const unsigned wmask = __ballot_sync(0xffffffffu, vec);

    if (vec) {
        const int coff = 4*u + 4;       // float4 covers elements 4u+4..4u+7
        const int j0 = 4*u + 3;         // pixels j0..j0+3

        // load current row r0 (incl. left-halo element 4u+3)
        int rb = r0*WW + coff;
        float4 tc = *(const float4*)(T + rb);
        float4 sc = *(const float4*)(S + rb);
        float4 kc = *(const float4*)(K + rb);
        float thc = __shfl_up_sync(wmask, tc.w, 1);
        float shc = __shfl_up_sync(wmask, sc.w, 1);
        float khc = __shfl_up_sync(wmask, kc.w, 1);
        if (lane == 0) { thc = T[rb-1]; shc = S[rb-1]; khc = K[rb-1]; }

        #pragma unroll 2
        for (int r = r0; r < r0 + RTILE; r++) {
            const bool lastrow = (r == HH-1);
            const int rn = (lastrow ? (r-1) : (r+1))*WW + coff;
            float4 tn = *(const float4*)(T + rn);
            float4 sn = *(const float4*)(S + rn);
            float4 kn = *(const float4*)(K + rn);
            float thn = __shfl_up_sync(wmask, tn.w, 1);
            float shn = __shfl_up_sync(wmask, sn.w, 1);
            float khn = __shfl_up_sync(wmask, kn.w, 1);
            if (lane == 0) { thn = T[rn-1]; shn = S[rn-1]; khn = K[rn-1]; }

            float t[5]  = {thc, tc.x, tc.y, tc.z, tc.w};
            float s[5]  = {shc, sc.x, sc.y, sc.z, sc.w};
            float k[5]  = {khc, kc.x, kc.y, kc.z, kc.w};
            float t2[4] = {thn, tn.x, tn.y, tn.z};
            float s2[4] = {shn, sn.x, sn.y, sn.z};
            float k2[4] = {khn, kn.x, kn.y, kn.z};

            float m[5], sm[5], m2[4], sm2[4];
            #pragma unroll
            for (int l = 0; l < 5; l++) { m[l] = (s[l] != 0.f) ? k[l] : 0.f; sm[l] = s[l]*k[l]; }
            #pragma unroll
            for (int l = 0; l < 4; l++) { m2[l] = (s2[l] != 0.f) ? k2[l] : 0.f; sm2[l] = s2[l]*k2[l]; }

            float wx4[4], wy4[4], gbx4[4], gby4[4], gsx4[4], gsy4[4];
            #pragma unroll
            for (int l = 0; l < 4; l++) {
                float gbx = t[l+1] - t[l];
                float gsx = sm[l+1] - sm[l];
                float gmx = m[l+1] - m[l];
                float gby, gsy, gmy;
                if (!lastrow) {
                    gby = t2[l]  - t[l];
                    gsy = sm2[l] - sm[l];
                    gmy = m2[l]  - m[l];
                } else {
                    gby = 0.f; gsy = 0.f;
                    gmy = m[l] - m2[l];
                }
                if (gmx != 0.f || gmy != 0.f) { gbx = 0.f; gby = 0.f; }

                float rc = fabsf(frcp(sm[l] + EPSV)) * NEG5LOG2E;
                float wx = m[l] * fex2(fabsf(gsx) * rc);
                float wy = m[l] * fex2(fabsf(gsy) * rc);

                float dx = wx * (gbx - gsx);
                float dy = wy * (gby - gsy);
                acc = fmaf(dx, dx, fmaf(dy, dy, acc));

                wx4[l] = wx;  wy4[l] = wy;
                gbx4[l] = gbx; gby4[l] = gby;
                gsx4[l] = gsx; gsy4[l] = gsy;
            }

            const int wb = r*W3 + j0;
            __stcs((float4*)(o + wb),        make_float4(wx4[0], wx4[1], wx4[2], wx4[3]));
            __stcs((float4*)(o + wb + WW),   make_float4(wy4[0], wy4[1], wy4[2], wy4[3]));
            __stcs((float4*)(o + wb + 2*WW), make_float4(0.f, 0.f, 0.f, 0.f));
            const int gb = GRAD_BASE + r*WW + j0;
            __stcs((float4*)(o + gb),          make_float4(gbx4[0], gbx4[1], gbx4[2], gbx4[3]));
            __stcs((float4*)(o + gb + NPIX),   make_float4(gby4[0], gby4[1], gby4[2], gby4[3]));
            __stcs((float4*)(o + gb + 2*NPIX), make_float4(gsx4[0], gsx4[1], gsx4[2], gsx4[3]));
            __stcs((float4*)(o + gb + 3*NPIX), make_float4(gsy4[0], gsy4[1], gsy4[2], gsy4[3]));

            // shift: next row becomes current
            tc = tn; sc = sn; kc = kn;
            thc = thn; shc = shn; khc = khn;
        }
    } else {
        // boundary thread: pixels j = 0,1,2 and j = 4095 for each row in strip
        for (int r = r0; r < r0 + RTILE; r++) {
            acc += do_pixel(r, 0,    T, K, S, o);
            acc += do_pixel(r, 1,    T, K, S, o);
            acc += do_pixel(r, 2,    T, K, S, o);
            acc += do_pixel(r, WW-1, T, K, S, o);
        }
    }

    // ---- deterministic block reduction -> per-block partial ----
    #pragma unroll
    for (int offs = 16; offs > 0; offs >>= 1)
        acc += __shfl_down_sync(0xffffffffu, acc, offs);

    __shared__ float wsum[BLK/32];
    __shared__ int   is_last;
    const int warp = threadIdx.x >> 5;
    if (lane == 0) wsum[warp] = acc;
    __syncthreads();
    if (threadIdx.x == 0) {
        float bsum = 0.f;
        #pragma unroll
        for (int w = 0; w < BLK/32; w++) bsum += wsum[w];
        g_partials[blockIdx.y * GRID_X + blockIdx.x] = bsum;
        unsigned int prev = atom_inc_acqrel(&g_counter);   // release orders store above
        is_last = (prev == NBLOCKS - 1u) ? 1 : 0;
    }
    __syncthreads();

    // ---- last block performs the final reduction (fixed order => deterministic) ----
    if (is_last) {
        asm volatile("fence.acquire.gpu;" ::: "memory");
        float a0 = 0.f, a1 = 0.f, a2 = 0.f, a3 = 0.f;
        const int base = threadIdx.x;
        #pragma unroll
        for (int r = 0; r < NBLOCKS / BLK; r += 4) {
            a0 += ldcg_f(&g_partials[base + (r+0)*BLK]);
            a1 += ldcg_f(&g_partials[base + (r+1)*BLK]);
            a2 += ldcg_f(&g_partials[base + (r+2)*BLK]);
            a3 += ldcg_f(&g_partials[base + (r+3)*BLK]);
        }
        float v = (a0 + a1) + (a2 + a3);
        #pragma unroll
        for (int offs = 16; offs > 0; offs >>= 1)
            v += __shfl_down_sync(0xffffffffu, v, offs);
        if (lane == 0) wsum[warp] = v;
        __syncthreads();
        if (threadIdx.x == 0) {
            float total = 0.f;
            #pragma unroll
            for (int w = 0; w < BLK/32; w++) total += wsum[w];
            out[0] = total * (1.0f / (float)NPIX);
            g_counter = 0u;   // reset for next graph replay
        }
    }
}

extern "C" void kernel_launch(void* const* d_in, const int* in_sizes, int n_in,
                              void* d_out, int out_size)
{
    const float* target = (const float*)d_in[0];
    const float* mask   = (const float*)d_in[1];
    const float* source = (const float*)d_in[2];
    float* out = (float*)d_out;

    dim3 grid(GRID_X, NROWBLK);
    wpbl_main<<<grid, BLK>>>(target, mask, source, out);
}

// round 9
// speedup vs baseline: 1.1211x; 1.1211x over previous
#include <cuda_runtime.h>
#include <cuda_bf16.h>

#define HH 4096
#define WW 4096
#define NPIX (HH*WW)           // 16777216
#define W3  (3*WW)             // 12288
#define GRAD_BASE 50331648     // H*3W, relative to o = out+1
#define GRID_X 4
#define BLK 256
#define NBLOCKS (GRID_X*HH)    // 16384

__device__ float g_partials[NBLOCKS];
__device__ unsigned int g_counter = 0u;

__device__ __forceinline__ float frcp(float x) {
    float y; asm("rcp.approx.f32 %0, %1;" : "=f"(y) : "f"(x)); return y;
}
__device__ __forceinline__ float fex2(float x) {
    float y; asm("ex2.approx.f32 %0, %1;" : "=f"(y) : "f"(x)); return y;
}
__device__ __forceinline__ float ldcg_f(const float* p) {
    float v; asm volatile("ld.global.cg.f32 %0, [%1];" : "=f"(v) : "l"(p)); return v;
}
__device__ __forceinline__ unsigned int atom_inc_acqrel(unsigned int* p) {
    unsigned int prev;
    asm volatile("atom.global.add.acq_rel.gpu.u32 %0, [%1], 1;"
                 : "=r"(prev) : "l"(p) : "memory");
    return prev;
}

__constant__ float NEG5LOG2E = -7.213475204444817f; // -5 / ln(2)
#define EPSV 1e-5f

// Fully general scalar path for boundary pixels.
__device__ __forceinline__ float do_pixel(int i, int j,
        const float* __restrict__ T, const float* __restrict__ K,
        const float* __restrict__ S, float* __restrict__ o)
{
    int idx = i*WW + j;
    float t = T[idx], s = S[idx], k = K[idx];
    float m  = (s != 0.f) ? k : 0.f;
    float sm = s * k;

    float gbx = 0.f, gsx = 0.f, gmx;
    if (j < WW-1) {
        float sr = S[idx+1], kr = K[idx+1];
        float mr = (sr != 0.f) ? kr : 0.f;
        gbx = T[idx+1] - t;
        gsx = sr*kr - sm;
        gmx = mr - m;
    } else {
        float sl = S[idx-1], kl = K[idx-1];
        gmx = m - ((sl != 0.f) ? kl : 0.f);
    }

    float gby = 0.f, gsy = 0.f, gmy;
    if (i < HH-1) {
        float sd = S[idx+WW], kd = K[idx+WW];
        float md = (sd != 0.f) ? kd : 0.f;
        gby = T[idx+WW] - t;
        gsy = sd*kd - sm;
        gmy = md - m;
    } else {
        float su = S[idx-WW], ku = K[idx-WW];
        gmy = m - ((su != 0.f) ? ku : 0.f);
    }

    if (gmx != 0.f || gmy != 0.f) { gbx = 0.f; gby = 0.f; }

    float rc = fabsf(frcp(sm + EPSV)) * NEG5LOG2E;
    float wx = m * fex2(fabsf(gsx) * rc);
    float wy = m * fex2(fabsf(gsy) * rc);

    int wb = i*W3 + j;
    __stcs(o + wb,        wx);
    __stcs(o + wb + WW,   wy);
    __stcs(o + wb + 2*WW, 0.f);
    int gb = GRAD_BASE + idx;
    __stcs(o + gb,          gbx);
    __stcs(o + gb + NPIX,   gby);
    __stcs(o + gb + 2*NPIX, gsx);
    __stcs(o + gb + 3*NPIX, gsy);

    float dx = wx * (gbx - gsx);
    float dy = wy * (gby - gsy);
    return fmaf(dx, dx, dy*dy);
}

__global__ __launch_bounds__(BLK)
void wpbl_main(const float* __restrict__ T, const float* __restrict__ K,
               const float* __restrict__ S, float* __restrict__ out)
{
    const int i = blockIdx.y;
    const int u = blockIdx.x * BLK + threadIdx.x;     // 0..1023
    float* o = out + 1;
    float acc = 0.f;

    if (u < 1016) {
        // vector path: pixels j = 4u+31 .. 4u+34  (31 <= j <= 4094)
        // => every warp's output float4 segment is 128B-aligned in out[]
        const int j0 = 4*u + 31;
        const bool last = (i == HH-1);
        const int rb = i*WW + 4*u + 28;
        const int r2 = (last ? (i-1) : (i+1))*WW + 4*u + 28;

        float4 ta = *(const float4*)(T + rb), tb = *(const float4*)(T + rb + 4);
        float4 sa = *(const float4*)(S + rb), sb = *(const float4*)(S + rb + 4);
        float4 ka = *(const float4*)(K + rb), kb = *(const float4*)(K + rb + 4);
        float4 t2a = *(const float4*)(T + r2), t2b = *(const float4*)(T + r2 + 4);
        float4 s2a = *(const float4*)(S + r2), s2b = *(const float4*)(S + r2 + 4);
        float4 k2a = *(const float4*)(K + r2), k2b = *(const float4*)(K + r2 + 4);

        float t[5] = {ta.w, tb.x, tb.y, tb.z, tb.w};
        float s[5] = {sa.w, sb.x, sb.y, sb.z, sb.w};
        float k[5] = {ka.w, kb.x, kb.y, kb.z, kb.w};
        float t2[4] = {t2a.w, t2b.x, t2b.y, t2b.z};
        float s2[4] = {s2a.w, s2b.x, s2b.y, s2b.z};
        float k2[4] = {k2a.w, k2b.x, k2b.y, k2b.z};

        float m[5], sm[5], m2[4], sm2[4];
        #pragma unroll
        for (int l = 0; l < 5; l++) { m[l] = (s[l] != 0.f) ? k[l] : 0.f; sm[l] = s[l]*k[l]; }
        #pragma unroll
        for (int l = 0; l < 4; l++) { m2[l] = (s2[l] != 0.f) ? k2[l] : 0.f; sm2[l] = s2[l]*k2[l]; }

        float wx4[4], wy4[4], gbx4[4], gby4[4], gsx4[4], gsy4[4];
        #pragma unroll
        for (int l = 0; l < 4; l++) {
            float gbx = t[l+1] - t[l];
            float gsx = sm[l+1] - sm[l];
            float gmx = m[l+1] - m[l];
            float gby, gsy, gmy;
            if (!last) {
                gby = t2[l]  - t[l];
                gsy = sm2[l] - sm[l];
                gmy = m2[l]  - m[l];
            } else {
                gby = 0.f; gsy = 0.f;
                gmy = m[l] - m2[l];
            }
            if (gmx != 0.f || gmy != 0.f) { gbx = 0.f; gby = 0.f; }

            float rc = fabsf(frcp(sm[l] + EPSV)) * NEG5LOG2E;
            float wx = m[l] * fex2(fabsf(gsx) * rc);
            float wy = m[l] * fex2(fabsf(gsy) * rc);

            float dx = wx * (gbx - gsx);
            float dy = wy * (gby - gsy);
            acc = fmaf(dx, dx, fmaf(dy, dy, acc));

            wx4[l] = wx;  wy4[l] = wy;
            gbx4[l] = gbx; gby4[l] = gby;
            gsx4[l] = gsx; gsy4[l] = gsy;
        }

        const int wb = i*W3 + j0;
        __stcs((float4*)(o + wb),        make_float4(wx4[0], wx4[1], wx4[2], wx4[3]));
        __stcs((float4*)(o + wb + WW),   make_float4(wy4[0], wy4[1], wy4[2], wy4[3]));
        __stcs((float4*)(o + wb + 2*WW), make_float4(0.f, 0.f, 0.f, 0.f));
        const int gb = GRAD_BASE + i*WW + j0;
        __stcs((float4*)(o + gb),          make_float4(gbx4[0], gbx4[1], gbx4[2], gbx4[3]));
        __stcs((float4*)(o + gb + NPIX),   make_float4(gby4[0], gby4[1], gby4[2], gby4[3]));
        __stcs((float4*)(o + gb + 2*NPIX), make_float4(gsx4[0], gsx4[1], gsx4[2], gsx4[3]));
        __stcs((float4*)(o + gb + 3*NPIX), make_float4(gsy4[0], gsy4[1], gsy4[2], gsy4[3]));
    } else {
        // boundary threads u = 1016..1023: pixels j = 0..30 and j = 4095
        const int h = u - 1016;            // 0..7
        if (h < 7) {
            acc += do_pixel(i, 4*h+0, T, K, S, o);
            acc += do_pixel(i, 4*h+1, T, K, S, o);
            acc += do_pixel(i, 4*h+2, T, K, S, o);
            acc += do_pixel(i, 4*h+3, T, K, S, o);
        } else {
            acc += do_pixel(i, 28,    T, K, S, o);
            acc += do_pixel(i, 29,    T, K, S, o);
            acc += do_pixel(i, 30,    T, K, S, o);
            acc += do_pixel(i, WW-1,  T, K, S, o);
        }
    }

    // ---- deterministic block reduction -> per-block partial ----
    #pragma unroll
    for (int off = 16; off > 0; off >>= 1)
        acc += __shfl_down_sync(0xffffffffu, acc, off);

    __shared__ float wsum[BLK/32];
    __shared__ int   is_last;
    const int lane = threadIdx.x & 31;
    const int warp = threadIdx.x >> 5;
    if (lane == 0) wsum[warp] = acc;
    __syncthreads();
    if (threadIdx.x == 0) {
        float bsum = 0.f;
        #pragma unroll
        for (int w = 0; w < BLK/32; w++) bsum += wsum[w];
        g_partials[blockIdx.y * GRID_X + blockIdx.x] = bsum;
        unsigned int prev = atom_inc_acqrel(&g_counter);   // release orders store above
        is_last = (prev == NBLOCKS - 1u) ? 1 : 0;
    }
    __syncthreads();

    // ---- last block performs the final reduction (fixed order => deterministic) ----
    if (is_last) {
        asm volatile("fence.acquire.gpu;" ::: "memory");
        float a0 = 0.f, a1 = 0.f, a2 = 0.f, a3 = 0.f;
        const int base = threadIdx.x;
        #pragma unroll
        for (int r = 0; r < NBLOCKS / BLK; r += 4) {
            a0 += ldcg_f(&g_partials[base + (r+0)*BLK]);
            a1 += ldcg_f(&g_partials[base + (r+1)*BLK]);
            a2 += ldcg_f(&g_partials[base + (r+2)*BLK]);
            a3 += ldcg_f(&g_partials[base + (r+3)*BLK]);
        }
        float v = (a0 + a1) + (a2 + a3);
        #pragma unroll
        for (int off = 16; off > 0; off >>= 1)
            v += __shfl_down_sync(0xffffffffu, v, off);
        if (lane == 0) wsum[warp] = v;
        __syncthreads();
        if (threadIdx.x == 0) {
            float total = 0.f;
            #pragma unroll
            for (int w = 0; w < BLK/32; w++) total += wsum[w];
            out[0] = total * (1.0f / (float)NPIX);
            g_counter = 0u;   // reset for next graph replay
        }
    }
}

extern "C" void kernel_launch(void* const* d_in, const int* in_sizes, int n_in,
                              void* d_out, int out_size)
{
    const float* target = (const float*)d_in[0];
    const float* mask   = (const float*)d_in[1];
    const float* source = (const float*)d_in[2];
    float* out = (float*)d_out;

    dim3 grid(GRID_X, HH);
    wpbl_main<<<grid, BLK>>>(target, mask, source, out);
}